// round 3
// baseline (speedup 1.0000x reference)
#include <cuda_runtime.h>

// Problem constants
#define BB 2
#define TT 2048
#define CC 1024
#define HH 16
#define HD 64

// Scratch (no cudaMalloc allowed): q,k,v in [B,H,T,hd], y in [B,T,C]
__device__ float g_q[BB * HH * TT * HD];
__device__ float g_k[BB * HH * TT * HD];
__device__ float g_v[BB * HH * TT * HD];
__device__ float g_y[BB * TT * CC];

// ---------------------------------------------------------------------------
// GEMM: C[M,N] = A[M,1024] @ W[1024,N] + bias
//   MODE 0: A = Ain (x), scatter output into g_q/g_k/g_v as [B,H,T,hd]
//   MODE 1: A = g_y,     write output to out [M,N]
// Tiles: BM=BN=128, BK=16, 256 threads, 8x8 microtile (split-m / split-n)
// ---------------------------------------------------------------------------
template <int MODE, int N>
__global__ __launch_bounds__(256, 2) void gemm_kernel(const float* __restrict__ Ain,
                                                      const float* __restrict__ W,
                                                      const float* __restrict__ bias,
                                                      float* __restrict__ out)
{
    __shared__ __align__(16) float As[16][132];  // [k][m], padded
    __shared__ __align__(16) float Bs[16][128];  // [k][n]

    const float* A = (MODE == 0) ? Ain : g_y;

    const int tid = threadIdx.x;
    const int tx = tid & 15;
    const int ty = tid >> 4;
    const int row0 = blockIdx.y * 128;
    const int col0 = blockIdx.x * 128;

    float acc[2][2][4][4];
#pragma unroll
    for (int ri = 0; ri < 2; ++ri)
#pragma unroll
        for (int ci = 0; ci < 2; ++ci)
#pragma unroll
            for (int i = 0; i < 4; ++i)
#pragma unroll
                for (int j = 0; j < 4; ++j) acc[ri][ci][i][j] = 0.0f;

    for (int kt = 0; kt < 64; ++kt) {
        const int k0 = kt * 16;
#pragma unroll
        for (int r = 0; r < 2; ++r) {
            const int idx = tid + r * 256;
            // A tile: 128 rows x 16 k -> transpose into As[k][m]
            const int m = idx >> 2, k4 = idx & 3;
            const float4 va = *(const float4*)(A + (size_t)(row0 + m) * 1024 + k0 + k4 * 4);
            As[k4 * 4 + 0][m] = va.x;
            As[k4 * 4 + 1][m] = va.y;
            As[k4 * 4 + 2][m] = va.z;
            As[k4 * 4 + 3][m] = va.w;
            // B tile: 16 k x 128 n, direct layout
            const int kk = idx >> 5, n4 = idx & 31;
            *(float4*)&Bs[kk][n4 * 4] =
                *(const float4*)(W + (size_t)(k0 + kk) * N + col0 + n4 * 4);
        }
        __syncthreads();

#pragma unroll
        for (int kk = 0; kk < 16; ++kk) {
            float a[8], bb[8];
            *(float4*)&a[0] = *(const float4*)&As[kk][ty * 4];
            *(float4*)&a[4] = *(const float4*)&As[kk][64 + ty * 4];
            *(float4*)&bb[0] = *(const float4*)&Bs[kk][tx * 4];
            *(float4*)&bb[4] = *(const float4*)&Bs[kk][64 + tx * 4];
#pragma unroll
            for (int ri = 0; ri < 2; ++ri)
#pragma unroll
                for (int i = 0; i < 4; ++i)
#pragma unroll
                    for (int ci = 0; ci < 2; ++ci)
#pragma unroll
                        for (int j = 0; j < 4; ++j)
                            acc[ri][ci][i][j] += a[ri * 4 + i] * bb[ci * 4 + j];
        }
        __syncthreads();
    }

    // Epilogue
#pragma unroll
    for (int ri = 0; ri < 2; ++ri)
#pragma unroll
        for (int i = 0; i < 4; ++i) {
            const int row = row0 + ri * 64 + ty * 4 + i;
#pragma unroll
            for (int ci = 0; ci < 2; ++ci) {
                const int colb = col0 + ci * 64 + tx * 4;  // 4 consecutive cols
                float4 v;
                v.x = acc[ri][ci][i][0] + bias[colb + 0];
                v.y = acc[ri][ci][i][1] + bias[colb + 1];
                v.z = acc[ri][ci][i][2] + bias[colb + 2];
                v.w = acc[ri][ci][i][3] + bias[colb + 3];
                if (MODE == 0) {
                    const int b = row >> 11;          // /2048
                    const int t = row & 2047;
                    const int which = colb >> 10;     // 0:q 1:k 2:v
                    const int rem = colb & 1023;
                    const int h = rem >> 6;
                    const int d = rem & 63;           // 4-aligned, contiguous
                    float* dst = (which == 0) ? g_q : (which == 1 ? g_k : g_v);
                    *(float4*)(dst + ((size_t)(b * HH + h) * TT + t) * HD + d) = v;
                } else {
                    *(float4*)(out + (size_t)row * N + colb) = v;
                }
            }
        }
}

// ---------------------------------------------------------------------------
// Flash attention (causal). One block = 64 q rows of one (b,h).
// smem: Qs[64][65], Ks[64][65] (reused as P), Vs[64][64]  => 49664 B dynamic
// 256 threads as 16x16: S microtile rows m=ty*4+i, cols n=tx+16j
// ---------------------------------------------------------------------------
__global__ __launch_bounds__(256) void attn_kernel()
{
    extern __shared__ __align__(16) float sm[];
    float* Qs = sm;              // 64*65
    float* Ks = sm + 64 * 65;    // 64*65 (also holds P)
    float* Vs = sm + 2 * 64 * 65; // 64*64

    const int tid = threadIdx.x;
    const int tx = tid & 15;
    const int ty = tid >> 4;
    const int qt = (int)gridDim.x - 1 - (int)blockIdx.x;  // heavy tiles first
    const int h = blockIdx.y;
    const int b = blockIdx.z;

    const size_t head_off = (size_t)(b * HH + h) * TT * HD;
    const float* qb = g_q + head_off;
    const float* kb = g_k + head_off;
    const float* vb = g_v + head_off;

    // Load Q tile (scaled by 1/sqrt(64)=0.125), transpose-free padded layout
#pragma unroll
    for (int r = 0; r < 4; ++r) {
        const int idx = tid + r * 256;
        const int m = idx >> 4, d4 = idx & 15;
        const float4 v = *(const float4*)(qb + (size_t)(qt * 64 + m) * HD + d4 * 4);
        Qs[m * 65 + d4 * 4 + 0] = v.x * 0.125f;
        Qs[m * 65 + d4 * 4 + 1] = v.y * 0.125f;
        Qs[m * 65 + d4 * 4 + 2] = v.z * 0.125f;
        Qs[m * 65 + d4 * 4 + 3] = v.w * 0.125f;
    }

    float O[4][4];
    float mrow[4], lrow[4];
#pragma unroll
    for (int i = 0; i < 4; ++i) {
        mrow[i] = -1e30f;
        lrow[i] = 0.0f;
#pragma unroll
        for (int j = 0; j < 4; ++j) O[i][j] = 0.0f;
    }

    for (int kt = 0; kt <= qt; ++kt) {
        __syncthreads();  // previous iter's P/V readers done before overwrite
#pragma unroll
        for (int r = 0; r < 4; ++r) {
            const int idx = tid + r * 256;
            const int m = idx >> 4, d4 = idx & 15;
            const float4 kv = *(const float4*)(kb + (size_t)(kt * 64 + m) * HD + d4 * 4);
            Ks[m * 65 + d4 * 4 + 0] = kv.x;
            Ks[m * 65 + d4 * 4 + 1] = kv.y;
            Ks[m * 65 + d4 * 4 + 2] = kv.z;
            Ks[m * 65 + d4 * 4 + 3] = kv.w;
            const float4 vv = *(const float4*)(vb + (size_t)(kt * 64 + m) * HD + d4 * 4);
            *(float4*)&Vs[m * 64 + d4 * 4] = vv;
        }
        __syncthreads();

        // S = Q K^T (scaled)
        float S[4][4];
#pragma unroll
        for (int i = 0; i < 4; ++i)
#pragma unroll
            for (int j = 0; j < 4; ++j) S[i][j] = 0.0f;

#pragma unroll 16
        for (int kk = 0; kk < 64; ++kk) {
            float a[4], bv[4];
#pragma unroll
            for (int i = 0; i < 4; ++i) a[i] = Qs[(ty * 4 + i) * 65 + kk];
#pragma unroll
            for (int j = 0; j < 4; ++j) bv[j] = Ks[(tx + 16 * j) * 65 + kk];
#pragma unroll
            for (int i = 0; i < 4; ++i)
#pragma unroll
                for (int j = 0; j < 4; ++j) S[i][j] += a[i] * bv[j];
        }

        // causal mask (only diagonal tile)
        if (kt == qt) {
#pragma unroll
            for (int i = 0; i < 4; ++i)
#pragma unroll
                for (int j = 0; j < 4; ++j)
                    if (tx + 16 * j > ty * 4 + i) S[i][j] = -1e30f;
        }

        // online softmax update
        float alpha[4];
#pragma unroll
        for (int i = 0; i < 4; ++i) {
            float tm = fmaxf(fmaxf(S[i][0], S[i][1]), fmaxf(S[i][2], S[i][3]));
            tm = fmaxf(tm, __shfl_xor_sync(0xffffffffu, tm, 8));
            tm = fmaxf(tm, __shfl_xor_sync(0xffffffffu, tm, 4));
            tm = fmaxf(tm, __shfl_xor_sync(0xffffffffu, tm, 2));
            tm = fmaxf(tm, __shfl_xor_sync(0xffffffffu, tm, 1));
            const float mn = fmaxf(mrow[i], tm);
            alpha[i] = __expf(mrow[i] - mn);
            mrow[i] = mn;
            float rs = 0.0f;
#pragma unroll
            for (int j = 0; j < 4; ++j) {
                S[i][j] = __expf(S[i][j] - mn);
                rs += S[i][j];
            }
            rs += __shfl_xor_sync(0xffffffffu, rs, 8);
            rs += __shfl_xor_sync(0xffffffffu, rs, 4);
            rs += __shfl_xor_sync(0xffffffffu, rs, 2);
            rs += __shfl_xor_sync(0xffffffffu, rs, 1);
            lrow[i] = lrow[i] * alpha[i] + rs;
#pragma unroll
            for (int j = 0; j < 4; ++j) O[i][j] *= alpha[i];
        }

        __syncthreads();  // K reads done before P overwrites the tile
#pragma unroll
        for (int i = 0; i < 4; ++i)
#pragma unroll
            for (int j = 0; j < 4; ++j)
                Ks[(ty * 4 + i) * 65 + tx + 16 * j] = S[i][j];
        __syncthreads();

        // O += P V
#pragma unroll 16
        for (int kk = 0; kk < 64; ++kk) {
            const float4 bv = *(const float4*)&Vs[kk * 64 + tx * 4];
#pragma unroll
            for (int i = 0; i < 4; ++i) {
                const float a = Ks[(ty * 4 + i) * 65 + kk];
                O[i][0] += a * bv.x;
                O[i][1] += a * bv.y;
                O[i][2] += a * bv.z;
                O[i][3] += a * bv.w;
            }
        }
    }

    // write y in [B,T,C] layout
#pragma unroll
    for (int i = 0; i < 4; ++i) {
        const float inv = 1.0f / lrow[i];
        const int t = qt * 64 + ty * 4 + i;
        float4 o;
        o.x = O[i][0] * inv;
        o.y = O[i][1] * inv;
        o.z = O[i][2] * inv;
        o.w = O[i][3] * inv;
        *(float4*)(g_y + (size_t)(b * TT + t) * CC + h * HD + tx * 4) = o;
    }
}

// ---------------------------------------------------------------------------
extern "C" void kernel_launch(void* const* d_in, const int* in_sizes, int n_in,
                              void* d_out, int out_size)
{
    (void)in_sizes; (void)n_in; (void)out_size;
    const float* x      = (const float*)d_in[0];
    const float* W_attn = (const float*)d_in[1];
    const float* b_attn = (const float*)d_in[2];
    const float* W_proj = (const float*)d_in[3];
    const float* b_proj = (const float*)d_in[4];
    float* out = (float*)d_out;

    const int smem_attn = (64 * 65 * 2 + 64 * 64) * 4;  // 49664 B
    cudaFuncSetAttribute(attn_kernel, cudaFuncAttributeMaxDynamicSharedMemorySize,
                         smem_attn);

    // 1) QKV GEMM + bias, scattered into [B,H,T,hd]
    dim3 g1(3072 / 128, 4096 / 128);
    gemm_kernel<0, 3072><<<g1, 256>>>(x, W_attn, b_attn, nullptr);

    // 2) causal flash attention -> g_y [B,T,C]
    dim3 ga(32, HH, BB);
    attn_kernel<<<ga, 256, smem_attn>>>();

    // 3) output projection + bias
    dim3 g2(1024 / 128, 4096 / 128);
    gemm_kernel<1, 1024><<<g2, 256>>>(nullptr, W_proj, b_proj, out);
}

// round 4
// speedup vs baseline: 2.1887x; 2.1887x over previous
#include <cuda_runtime.h>
#include <cstdint>

// Problem constants
#define BB 2
#define TT 2048
#define CC 1024
#define HH 16
#define HD 64

// Scratch (no cudaMalloc allowed): q,k,v in [B,H,T,hd], y in [B,T,C]
__device__ float g_q[BB * HH * TT * HD];
__device__ float g_k[BB * HH * TT * HD];
__device__ float g_v[BB * HH * TT * HD];
__device__ float g_y[BB * TT * CC];

// ---------------------------------------------------------------------------
// helpers
// ---------------------------------------------------------------------------
__device__ __forceinline__ uint32_t f2tf(float x) {
    uint32_t u;
    asm("cvt.rna.tf32.f32 %0, %1;" : "=r"(u) : "f"(x));
    return u;
}

__device__ __forceinline__ void mma8(float* c, uint32_t a0, uint32_t a1,
                                     uint32_t a2, uint32_t a3,
                                     uint32_t b0, uint32_t b1) {
    asm volatile(
        "mma.sync.aligned.m16n8k8.row.col.f32.tf32.tf32.f32 "
        "{%0,%1,%2,%3}, {%4,%5,%6,%7}, {%8,%9}, {%0,%1,%2,%3};"
        : "+f"(c[0]), "+f"(c[1]), "+f"(c[2]), "+f"(c[3])
        : "r"(a0), "r"(a1), "r"(a2), "r"(a3), "r"(b0), "r"(b1));
}

// ---------------------------------------------------------------------------
// GEMM: C[M,N] = A[M,1024] @ W[1024,N] + bias   (tf32 mma, fp32 accum)
//   MODE 0: A = Ain (x), scatter output into g_q/g_k/g_v as [B,H,T,hd]
//   MODE 1: A = g_y,     write output to out [M,N]
// Tiles: BM=BN=128, BK=16, 256 threads (8 warps 4m x 2n, 32x64 per warp)
// ---------------------------------------------------------------------------
template <int MODE, int N>
__global__ __launch_bounds__(256) void gemm_mma(const float* __restrict__ Ain,
                                                const float* __restrict__ W,
                                                const float* __restrict__ bias,
                                                float* __restrict__ out)
{
    __shared__ __align__(16) float As[2][128 * 20];  // [m][k], pad 20 (conflict-free frags)
    __shared__ __align__(16) float Bs[2][16 * 136];  // [k][n], pad 136

    const float* A = (MODE == 0) ? Ain : g_y;

    const int tid = threadIdx.x;
    const int lane = tid & 31;
    const int g = lane >> 2, t4 = lane & 3;
    const int w = tid >> 5;
    const int wm = w & 3, wn = w >> 1 >> 1;  // wn = w>>2
    const int row0 = blockIdx.y * 128, col0 = blockIdx.x * 128;

    float4 pA[2], pB[2];

    auto loadG = [&](int kt) {
#pragma unroll
        for (int r = 0; r < 2; ++r) {
            const int idx = tid + r * 256;
            const int m = idx >> 2, c = idx & 3;
            pA[r] = *(const float4*)(A + (size_t)(row0 + m) * 1024 + kt * 16 + c * 4);
            const int k = idx >> 5, n4 = idx & 31;
            pB[r] = *(const float4*)(W + (size_t)(kt * 16 + k) * N + col0 + n4 * 4);
        }
    };
    auto storeS = [&](int buf) {
#pragma unroll
        for (int r = 0; r < 2; ++r) {
            const int idx = tid + r * 256;
            const int m = idx >> 2, c = idx & 3;
            float* pa = &As[buf][m * 20 + c * 4];
            pa[0] = __uint_as_float(f2tf(pA[r].x));
            pa[1] = __uint_as_float(f2tf(pA[r].y));
            pa[2] = __uint_as_float(f2tf(pA[r].z));
            pa[3] = __uint_as_float(f2tf(pA[r].w));
            const int k = idx >> 5, n4 = idx & 31;
            float* pb = &Bs[buf][k * 136 + n4 * 4];
            pb[0] = __uint_as_float(f2tf(pB[r].x));
            pb[1] = __uint_as_float(f2tf(pB[r].y));
            pb[2] = __uint_as_float(f2tf(pB[r].z));
            pb[3] = __uint_as_float(f2tf(pB[r].w));
        }
    };

    float acc[2][8][4];
#pragma unroll
    for (int mi = 0; mi < 2; ++mi)
#pragma unroll
        for (int ni = 0; ni < 8; ++ni)
#pragma unroll
            for (int j = 0; j < 4; ++j) acc[mi][ni][j] = 0.0f;

    loadG(0);
    storeS(0);
    __syncthreads();

    for (int kt = 0; kt < 64; ++kt) {
        const int cur = kt & 1;
        if (kt < 63) loadG(kt + 1);

#pragma unroll
        for (int s = 0; s < 2; ++s) {
            uint32_t a[2][4];
#pragma unroll
            for (int mi = 0; mi < 2; ++mi) {
                const float* base = &As[cur][(wm * 32 + mi * 16) * 20];
                a[mi][0] = __float_as_uint(base[(g) * 20 + s * 8 + t4]);
                a[mi][1] = __float_as_uint(base[(g + 8) * 20 + s * 8 + t4]);
                a[mi][2] = __float_as_uint(base[(g) * 20 + s * 8 + t4 + 4]);
                a[mi][3] = __float_as_uint(base[(g + 8) * 20 + s * 8 + t4 + 4]);
            }
#pragma unroll
            for (int ni = 0; ni < 8; ++ni) {
                const int cb = wn * 64 + ni * 8 + g;
                const uint32_t b0 = __float_as_uint(Bs[cur][(s * 8 + t4) * 136 + cb]);
                const uint32_t b1 = __float_as_uint(Bs[cur][(s * 8 + t4 + 4) * 136 + cb]);
                mma8(acc[0][ni], a[0][0], a[0][1], a[0][2], a[0][3], b0, b1);
                mma8(acc[1][ni], a[1][0], a[1][1], a[1][2], a[1][3], b0, b1);
            }
        }

        if (kt < 63) storeS(cur ^ 1);
        __syncthreads();
    }

    // Epilogue: c-frag rows (g, g+8), cols (2*t4, 2*t4+1)
#pragma unroll
    for (int mi = 0; mi < 2; ++mi) {
        const int r_lo = row0 + wm * 32 + mi * 16 + g;
#pragma unroll
        for (int ni = 0; ni < 8; ++ni) {
            const int c = col0 + wn * 64 + ni * 8 + t4 * 2;
            float2 vlo, vhi;
            vlo.x = acc[mi][ni][0] + bias[c];
            vlo.y = acc[mi][ni][1] + bias[c + 1];
            vhi.x = acc[mi][ni][2] + bias[c];
            vhi.y = acc[mi][ni][3] + bias[c + 1];
            if (MODE == 0) {
                const int which = c >> 10;
                const int rem = c & 1023;
                const int hh = rem >> 6;
                const int d = rem & 63;  // even, pair stays inside head
                float* dst = (which == 0) ? g_q : (which == 1 ? g_k : g_v);
#pragma unroll
                for (int hv = 0; hv < 2; ++hv) {
                    const int row = r_lo + hv * 8;
                    const int bb = row >> 11;
                    const int t = row & 2047;
                    *(float2*)(dst + ((size_t)(bb * HH + hh) * TT + t) * HD + d) =
                        hv ? vhi : vlo;
                }
            } else {
                *(float2*)(out + (size_t)r_lo * N + c) = vlo;
                *(float2*)(out + (size_t)(r_lo + 8) * N + c) = vhi;
            }
        }
    }
}

// ---------------------------------------------------------------------------
// Flash attention (causal), tf32 mma. One block = 128 q rows of one (b,h).
// 8 warps, m-split (warp = 16 q-rows x full 64 kv cols) -> warp-local softmax.
// K/Q smem columns permuted in-group so fragments are float2 LDS.
// P c-frag -> a-frag conversion via quad shuffles (no smem round trip).
// smem: Qs[128][68] + Ks[64][68] + Vs[64][72] = 70656 B dynamic
// ---------------------------------------------------------------------------
__global__ __launch_bounds__(256, 2) void attn_mma()
{
    extern __shared__ __align__(16) float sm[];
    float* Qs = sm;                  // 128*68
    float* Ks = sm + 128 * 68;       // 64*68
    float* Vs = Ks + 64 * 68;        // 64*72

    const int tid = threadIdx.x;
    const int lane = tid & 31;
    const int w = tid >> 5;
    const int g = lane >> 2, t4 = lane & 3;
    const int qt = 15 - (int)blockIdx.x;  // heavy tiles first
    const int h = blockIdx.y;
    const int b = blockIdx.z;

    const size_t ho = (size_t)(b * HH + h) * TT * HD;
    const float* qb = g_q + ho;
    const float* kb = g_k + ho;
    const float* vb = g_v + ho;

    // Load Q (scale 1/8, tf32, column-permuted: group col 4b+q -> 2q+b)
#pragma unroll
    for (int r = 0; r < 8; ++r) {
        const int idx = tid + r * 256;
        const int m = idx >> 4, d4 = idx & 15;
        const float4 v = *(const float4*)(qb + (size_t)(qt * 128 + m) * HD + d4 * 4);
        const int base = m * 68 + (d4 >> 1) * 8 + (d4 & 1);
        Qs[base + 0] = __uint_as_float(f2tf(v.x * 0.125f));
        Qs[base + 2] = __uint_as_float(f2tf(v.y * 0.125f));
        Qs[base + 4] = __uint_as_float(f2tf(v.z * 0.125f));
        Qs[base + 6] = __uint_as_float(f2tf(v.w * 0.125f));
    }

    float O[8][4];
#pragma unroll
    for (int n = 0; n < 8; ++n)
#pragma unroll
        for (int j = 0; j < 4; ++j) O[n][j] = 0.0f;
    float m_lo = -1e30f, m_hi = -1e30f, l_lo = 0.0f, l_hi = 0.0f;

    const int rlo = qt * 128 + w * 16 + g;  // this thread's low q-row
    const int nkt = 2 * qt + 2;

    for (int kt = 0; kt < nkt; ++kt) {
        __syncthreads();  // previous iter done reading Ks/Vs
#pragma unroll
        for (int r = 0; r < 4; ++r) {
            const int idx = tid + r * 256;
            const int m = idx >> 4, d4 = idx & 15;
            const float4 kv = *(const float4*)(kb + (size_t)(kt * 64 + m) * HD + d4 * 4);
            const int base = m * 68 + (d4 >> 1) * 8 + (d4 & 1);
            Ks[base + 0] = __uint_as_float(f2tf(kv.x));
            Ks[base + 2] = __uint_as_float(f2tf(kv.y));
            Ks[base + 4] = __uint_as_float(f2tf(kv.z));
            Ks[base + 6] = __uint_as_float(f2tf(kv.w));
            const float4 vv = *(const float4*)(vb + (size_t)(kt * 64 + m) * HD + d4 * 4);
            float4 vt;
            vt.x = __uint_as_float(f2tf(vv.x));
            vt.y = __uint_as_float(f2tf(vv.y));
            vt.z = __uint_as_float(f2tf(vv.z));
            vt.w = __uint_as_float(f2tf(vv.w));
            *(float4*)&Vs[m * 72 + d4 * 4] = vt;
        }
        __syncthreads();

        // S = Q K^T  (16x64 per warp: 8 n8 tiles, 8 k8 steps)
        float Sa[8][4];
#pragma unroll
        for (int n = 0; n < 8; ++n)
#pragma unroll
            for (int j = 0; j < 4; ++j) Sa[n][j] = 0.0f;

#pragma unroll
        for (int s = 0; s < 8; ++s) {
            const float2 qlo = *(const float2*)&Qs[(w * 16 + g) * 68 + s * 8 + t4 * 2];
            const float2 qhi = *(const float2*)&Qs[(w * 16 + g + 8) * 68 + s * 8 + t4 * 2];
            const uint32_t a0 = __float_as_uint(qlo.x);
            const uint32_t a1 = __float_as_uint(qhi.x);
            const uint32_t a2 = __float_as_uint(qlo.y);
            const uint32_t a3 = __float_as_uint(qhi.y);
#pragma unroll
            for (int n = 0; n < 8; ++n) {
                const float2 kk = *(const float2*)&Ks[(n * 8 + g) * 68 + s * 8 + t4 * 2];
                mma8(Sa[n], a0, a1, a2, a3,
                     __float_as_uint(kk.x), __float_as_uint(kk.y));
            }
        }

        // causal mask (only last two kv tiles can cross the diagonal)
        if (kt >= 2 * qt) {
#pragma unroll
            for (int n = 0; n < 8; ++n) {
                const int c = kt * 64 + n * 8 + t4 * 2;
                if (c > rlo) Sa[n][0] = -1e30f;
                if (c + 1 > rlo) Sa[n][1] = -1e30f;
                if (c > rlo + 8) Sa[n][2] = -1e30f;
                if (c + 1 > rlo + 8) Sa[n][3] = -1e30f;
            }
        }

        // online softmax (rows g and g+8, warp-local: reduce over quad)
        float mx_lo = -1e30f, mx_hi = -1e30f;
#pragma unroll
        for (int n = 0; n < 8; ++n) {
            mx_lo = fmaxf(mx_lo, fmaxf(Sa[n][0], Sa[n][1]));
            mx_hi = fmaxf(mx_hi, fmaxf(Sa[n][2], Sa[n][3]));
        }
        mx_lo = fmaxf(mx_lo, __shfl_xor_sync(0xffffffffu, mx_lo, 1));
        mx_lo = fmaxf(mx_lo, __shfl_xor_sync(0xffffffffu, mx_lo, 2));
        mx_hi = fmaxf(mx_hi, __shfl_xor_sync(0xffffffffu, mx_hi, 1));
        mx_hi = fmaxf(mx_hi, __shfl_xor_sync(0xffffffffu, mx_hi, 2));
        const float mn_lo = fmaxf(m_lo, mx_lo);
        const float mn_hi = fmaxf(m_hi, mx_hi);
        const float al_lo = __expf(m_lo - mn_lo);
        const float al_hi = __expf(m_hi - mn_hi);
        m_lo = mn_lo;
        m_hi = mn_hi;
        float rs_lo = 0.0f, rs_hi = 0.0f;
#pragma unroll
        for (int n = 0; n < 8; ++n) {
            Sa[n][0] = __expf(Sa[n][0] - mn_lo);
            Sa[n][1] = __expf(Sa[n][1] - mn_lo);
            Sa[n][2] = __expf(Sa[n][2] - mn_hi);
            Sa[n][3] = __expf(Sa[n][3] - mn_hi);
            rs_lo += Sa[n][0] + Sa[n][1];
            rs_hi += Sa[n][2] + Sa[n][3];
        }
        rs_lo += __shfl_xor_sync(0xffffffffu, rs_lo, 1);
        rs_lo += __shfl_xor_sync(0xffffffffu, rs_lo, 2);
        rs_hi += __shfl_xor_sync(0xffffffffu, rs_hi, 1);
        rs_hi += __shfl_xor_sync(0xffffffffu, rs_hi, 2);
        l_lo = l_lo * al_lo + rs_lo;
        l_hi = l_hi * al_hi + rs_hi;
#pragma unroll
        for (int n = 0; n < 8; ++n) {
            O[n][0] *= al_lo;
            O[n][1] *= al_lo;
            O[n][2] *= al_hi;
            O[n][3] *= al_hi;
        }

        // O += P V : convert c-frag (cols 2t4,2t4+1) -> a-frag (cols t4,t4+4)
        const int src = (lane & ~3) | (t4 >> 1);
        const int src2 = src + 2;
        const bool odd = (t4 & 1);
#pragma unroll
        for (int j = 0; j < 8; ++j) {
            float x0 = __shfl_sync(0xffffffffu, Sa[j][0], src);
            float x1 = __shfl_sync(0xffffffffu, Sa[j][1], src);
            float y0 = __shfl_sync(0xffffffffu, Sa[j][0], src2);
            float y1 = __shfl_sync(0xffffffffu, Sa[j][1], src2);
            const uint32_t pa0 = f2tf(odd ? x1 : x0);
            const uint32_t pa2 = f2tf(odd ? y1 : y0);
            x0 = __shfl_sync(0xffffffffu, Sa[j][2], src);
            x1 = __shfl_sync(0xffffffffu, Sa[j][3], src);
            y0 = __shfl_sync(0xffffffffu, Sa[j][2], src2);
            y1 = __shfl_sync(0xffffffffu, Sa[j][3], src2);
            const uint32_t pa1 = f2tf(odd ? x1 : x0);
            const uint32_t pa3 = f2tf(odd ? y1 : y0);
#pragma unroll
            for (int n = 0; n < 8; ++n) {
                const uint32_t b0 = __float_as_uint(Vs[(j * 8 + t4) * 72 + n * 8 + g]);
                const uint32_t b1 = __float_as_uint(Vs[(j * 8 + t4 + 4) * 72 + n * 8 + g]);
                mma8(O[n], pa0, pa1, pa2, pa3, b0, b1);
            }
        }
    }

    // write y in [B,T,C]
    const float inv_lo = 1.0f / l_lo;
    const float inv_hi = 1.0f / l_hi;
#pragma unroll
    for (int n = 0; n < 8; ++n) {
        float2 vlo, vhi;
        vlo.x = O[n][0] * inv_lo;
        vlo.y = O[n][1] * inv_lo;
        vhi.x = O[n][2] * inv_hi;
        vhi.y = O[n][3] * inv_hi;
        const int col = h * HD + n * 8 + t4 * 2;
        *(float2*)(g_y + (size_t)(b * TT + rlo) * CC + col) = vlo;
        *(float2*)(g_y + (size_t)(b * TT + rlo + 8) * CC + col) = vhi;
    }
}

// ---------------------------------------------------------------------------
extern "C" void kernel_launch(void* const* d_in, const int* in_sizes, int n_in,
                              void* d_out, int out_size)
{
    (void)in_sizes; (void)n_in; (void)out_size;
    const float* x      = (const float*)d_in[0];
    const float* W_attn = (const float*)d_in[1];
    const float* b_attn = (const float*)d_in[2];
    const float* W_proj = (const float*)d_in[3];
    const float* b_proj = (const float*)d_in[4];
    float* out = (float*)d_out;

    const int smem_attn = (128 * 68 + 64 * 68 + 64 * 72) * 4;  // 70656 B
    cudaFuncSetAttribute(attn_mma, cudaFuncAttributeMaxDynamicSharedMemorySize,
                         smem_attn);

    // 1) QKV GEMM + bias, scattered into [B,H,T,hd]
    dim3 g1(3072 / 128, 4096 / 128);
    gemm_mma<0, 3072><<<g1, 256>>>(x, W_attn, b_attn, nullptr);

    // 2) causal flash attention -> g_y [B,T,C]
    dim3 ga(16, HH, BB);
    attn_mma<<<ga, 256, smem_attn>>>();

    // 3) output projection + bias
    dim3 g2(1024 / 128, 4096 / 128);
    gemm_mma<1, 1024><<<g2, 256>>>(nullptr, W_proj, b_proj, out);
}

// round 6
// speedup vs baseline: 3.0415x; 1.3896x over previous
#include <cuda_runtime.h>
#include <cstdint>

// Problem constants
#define BB 2
#define TT 2048
#define CC 1024
#define HH 16
#define HD 64

// Scratch (no cudaMalloc): all tf32-pre-rounded where consumed by mma.
// g_q/g_k: [B,H,T,64] with d-dim sigma-permuted (q pre-scaled by 0.125)
// g_v:     [B,H,T,64] natural
// g_y:     [B,T,C] rounded + sigma-permuted on C (feeds proj GEMM)
// g_xr:    x rounded + sigma-permuted on K
// g_war/g_wpr: W transposed [N][K], rounded, sigma-permuted on K
__device__ __align__(256) float g_q[BB * HH * TT * HD];
__device__ __align__(256) float g_k[BB * HH * TT * HD];
__device__ __align__(256) float g_v[BB * HH * TT * HD];
__device__ __align__(256) float g_y[BB * TT * CC];
__device__ __align__(256) float g_xr[BB * TT * CC];
__device__ __align__(256) float g_war[3 * CC * CC];
__device__ __align__(256) float g_wpr[CC * CC];

// ---------------------------------------------------------------------------
// helpers
// ---------------------------------------------------------------------------
__device__ __forceinline__ uint32_t f2tf(float x) {
    uint32_t u;
    asm("cvt.rna.tf32.f32 %0, %1;" : "=r"(u) : "f"(x));
    return u;
}
__device__ __forceinline__ float f2tff(float x) { return __uint_as_float(f2tf(x)); }

__device__ __forceinline__ void mma8(float* c, uint32_t a0, uint32_t a1,
                                     uint32_t a2, uint32_t a3,
                                     uint32_t b0, uint32_t b1) {
    asm volatile(
        "mma.sync.aligned.m16n8k8.row.col.f32.tf32.tf32.f32 "
        "{%0,%1,%2,%3}, {%4,%5,%6,%7}, {%8,%9}, {%0,%1,%2,%3};"
        : "+f"(c[0]), "+f"(c[1]), "+f"(c[2]), "+f"(c[3])
        : "r"(a0), "r"(a1), "r"(a2), "r"(a3), "r"(b0), "r"(b1));
}

__device__ __forceinline__ void cpa16(uint32_t dst, const void* src) {
    asm volatile("cp.async.cg.shared.global [%0], [%1], 16;" :: "r"(dst), "l"(src));
}
__device__ __forceinline__ void cp_commit() {
    asm volatile("cp.async.commit_group;");
}
template <int N>
__device__ __forceinline__ void cp_wait() {
    asm volatile("cp.async.wait_group %0;" :: "n"(N));
}

// sigma: logical k (within 8) -> physical slot;  isig: inverse
__device__ __forceinline__ int sig8(int l) { return ((l & 3) << 1) | (l >> 2); }
__device__ __forceinline__ int isig8(int p) { return ((p & 1) << 2) | ((p >> 1) & 3); }

// ---------------------------------------------------------------------------
// prep kernels: round to tf32 (+ transpose / k-permute)
// ---------------------------------------------------------------------------
__global__ void prep_x(const float* __restrict__ x) {
    const int i = blockIdx.x * blockDim.x + threadIdx.x;
    const int src = (i & ~7) | isig8(i & 7);
    g_xr[i] = f2tff(x[src]);
}

// W [1024 x Nc] row-major -> Wt [Nc x 1024], rounded, k-permuted
__global__ void prep_w(const float* __restrict__ W, int Nc, int which) {
    __shared__ float t[32][33];
    float* Wt = which ? g_wpr : g_war;
    const int n0 = blockIdx.x * 32, k0 = blockIdx.y * 32;
    const int tx = threadIdx.x, ty0 = threadIdx.y;
#pragma unroll
    for (int i = 0; i < 4; ++i) {
        const int ty = ty0 + i * 8;
        t[ty][tx] = W[(size_t)(k0 + ty) * Nc + n0 + tx];
    }
    __syncthreads();
    const int p = (tx & ~7) | sig8(tx & 7);
#pragma unroll
    for (int i = 0; i < 4; ++i) {
        const int ty = ty0 + i * 8;
        Wt[(size_t)(n0 + ty) * 1024 + k0 + p] = f2tff(t[tx][ty]);
    }
}

// ---------------------------------------------------------------------------
// GEMM: C[M,N] = A[M,1024] @ W[1024,N] + bias  (tf32 mma, cp.async 2-stage)
//   MODE 0: A=g_xr, Wt=g_war, scatter q/k/v (q scaled+rounded+permuted,
//           k rounded+permuted, v rounded natural)
//   MODE 1: A=g_y,  Wt=g_wpr, out full fp32
// BM=BN=128, BK=32, 256 threads (8 warps 4m x 2n), both tiles [128][40]
// ---------------------------------------------------------------------------
template <int MODE, int NW>
__global__ __launch_bounds__(256, 2) void gemm_mma(const float* __restrict__ bias,
                                                   float* __restrict__ out)
{
    extern __shared__ __align__(16) float smem[];
    float* As = smem;                // [2][128*40]
    float* Bs = smem + 2 * 5120;     // [2][128*40]
    const uint32_t sA = (uint32_t)__cvta_generic_to_shared(As);
    const uint32_t sB = (uint32_t)__cvta_generic_to_shared(Bs);

    const float* A  = (MODE == 0) ? g_xr : g_y;
    const float* Wt = (MODE == 0) ? g_war : g_wpr;

    const int tid = threadIdx.x;
    const int lane = tid & 31;
    const int g = lane >> 2, t4 = lane & 3;
    const int w = tid >> 5;
    const int wm = w & 3, wn = w >> 2;
    const int row0 = blockIdx.y * 128, col0 = blockIdx.x * 128;

    auto issue = [&](int kt, int buf) {
#pragma unroll
        for (int r = 0; r < 4; ++r) {
            const int idx = tid + r * 256;
            const int m = idx >> 3, c = idx & 7;
            const uint32_t off = (uint32_t)(buf * 5120 + m * 40 + c * 4) * 4u;
            cpa16(sA + off, A  + (size_t)(row0 + m) * 1024 + kt * 32 + c * 4);
            cpa16(sB + off, Wt + (size_t)(col0 + m) * 1024 + kt * 32 + c * 4);
        }
        cp_commit();
    };

    float acc[2][8][4];
#pragma unroll
    for (int mi = 0; mi < 2; ++mi)
#pragma unroll
        for (int ni = 0; ni < 8; ++ni)
#pragma unroll
            for (int j = 0; j < 4; ++j) acc[mi][ni][j] = 0.0f;

    issue(0, 0);
    for (int kt = 0; kt < 32; ++kt) {
        if (kt < 31) { issue(kt + 1, (kt + 1) & 1); cp_wait<1>(); }
        else cp_wait<0>();
        __syncthreads();
        const float* Ab = As + (kt & 1) * 5120;
        const float* Bb = Bs + (kt & 1) * 5120;
#pragma unroll
        for (int s = 0; s < 4; ++s) {
            uint32_t a[2][4];
#pragma unroll
            for (int mi = 0; mi < 2; ++mi) {
                const float2 lo = *(const float2*)&Ab[(wm * 32 + mi * 16 + g) * 40 + s * 8 + 2 * t4];
                const float2 hi = *(const float2*)&Ab[(wm * 32 + mi * 16 + g + 8) * 40 + s * 8 + 2 * t4];
                a[mi][0] = __float_as_uint(lo.x);
                a[mi][1] = __float_as_uint(hi.x);
                a[mi][2] = __float_as_uint(lo.y);
                a[mi][3] = __float_as_uint(hi.y);
            }
#pragma unroll
            for (int ni = 0; ni < 8; ++ni) {
                const float2 bb = *(const float2*)&Bb[(wn * 64 + ni * 8 + g) * 40 + s * 8 + 2 * t4];
                const uint32_t b0 = __float_as_uint(bb.x);
                const uint32_t b1 = __float_as_uint(bb.y);
                mma8(acc[0][ni], a[0][0], a[0][1], a[0][2], a[0][3], b0, b1);
                mma8(acc[1][ni], a[1][0], a[1][1], a[1][2], a[1][3], b0, b1);
            }
        }
        __syncthreads();
    }

    // Epilogue: c-frag rows (g, g+8), cols (2t4, 2t4+1)
#pragma unroll
    for (int mi = 0; mi < 2; ++mi) {
        const int r_lo = row0 + wm * 32 + mi * 16 + g;
#pragma unroll
        for (int ni = 0; ni < 8; ++ni) {
            const int c = col0 + wn * 64 + ni * 8 + t4 * 2;
            const float v00 = acc[mi][ni][0] + bias[c];
            const float v01 = acc[mi][ni][1] + bias[c + 1];
            const float v10 = acc[mi][ni][2] + bias[c];
            const float v11 = acc[mi][ni][3] + bias[c + 1];
            if (MODE == 0) {
                const int which = c >> 10;
                const int rem = c & 1023;
                const int hh = rem >> 6;
                const int dl = rem & 63;
                const int bb0 = r_lo >> 11, t0 = r_lo & 2047;
                const int bb1 = (r_lo + 8) >> 11, t1 = (r_lo + 8) & 2047;
                if (which == 2) {
                    float2 lo, hi;
                    lo.x = f2tff(v00); lo.y = f2tff(v01);
                    hi.x = f2tff(v10); hi.y = f2tff(v11);
                    *(float2*)(g_v + ((size_t)(bb0 * HH + hh) * TT + t0) * HD + dl) = lo;
                    *(float2*)(g_v + ((size_t)(bb1 * HH + hh) * TT + t1) * HD + dl) = hi;
                } else {
                    float* dst = which ? g_k : g_q;
                    const float sc = which ? 1.0f : 0.125f;
                    const int d0 = (dl & ~7) | sig8(dl & 7);
                    const int d1 = (dl & ~7) | sig8((dl & 7) + 1);
                    float* p0 = dst + ((size_t)(bb0 * HH + hh) * TT + t0) * HD;
                    float* p1 = dst + ((size_t)(bb1 * HH + hh) * TT + t1) * HD;
                    p0[d0] = f2tff(v00 * sc);
                    p0[d1] = f2tff(v01 * sc);
                    p1[d0] = f2tff(v10 * sc);
                    p1[d1] = f2tff(v11 * sc);
                }
            } else {
                float2 lo, hi;
                lo.x = v00; lo.y = v01;
                hi.x = v10; hi.y = v11;
                *(float2*)(out + (size_t)r_lo * NW + c) = lo;
                *(float2*)(out + (size_t)(r_lo + 8) * NW + c) = hi;
            }
        }
    }
}

// ---------------------------------------------------------------------------
// Flash attention (causal), tf32 mma, cp.async double-buffered K/V.
// One block = 128 q rows of one (b,h); 8 warps m-split (warp-local softmax).
// smem: Qs[128][72] + 2x Ks[64][72] + 2x Vs[64][72] = 110592 B
// ---------------------------------------------------------------------------
__global__ __launch_bounds__(256, 2) void attn_mma()
{
    extern __shared__ __align__(16) float sm[];
    float* Qs = sm;  // 128*72 = 9216
    const uint32_t sQ = (uint32_t)__cvta_generic_to_shared(sm);

    const int tid = threadIdx.x;
    const int lane = tid & 31;
    const int w = tid >> 5;
    const int g = lane >> 2, t4 = lane & 3;
    const int qt = 15 - (int)blockIdx.x;  // heavy tiles first
    const int h = blockIdx.y, b = blockIdx.z;

    const size_t ho = (size_t)(b * HH + h) * TT * HD;
    const float* qb = g_q + ho;
    const float* kb = g_k + ho;
    const float* vb = g_v + ho;

    // Q tile (pre-scaled/rounded/permuted in gmem)
#pragma unroll
    for (int r = 0; r < 8; ++r) {
        const int idx = tid + r * 256;
        const int m = idx >> 4, d4 = idx & 15;
        cpa16(sQ + (uint32_t)(m * 72 + d4 * 4) * 4u,
              qb + (size_t)(qt * 128 + m) * HD + d4 * 4);
    }
    auto issueKV = [&](int kt, int buf) {
#pragma unroll
        for (int r = 0; r < 4; ++r) {
            const int idx = tid + r * 256;
            const int m = idx >> 4, d4 = idx & 15;
            const uint32_t off = (uint32_t)(m * 72 + d4 * 4) * 4u;
            cpa16(sQ + (uint32_t)(9216 + buf * 4608) * 4u + off,
                  kb + (size_t)(kt * 64 + m) * HD + d4 * 4);
            cpa16(sQ + (uint32_t)(18432 + buf * 4608) * 4u + off,
                  vb + (size_t)(kt * 64 + m) * HD + d4 * 4);
        }
        cp_commit();
    };
    issueKV(0, 0);  // group 0 = Q + K0 + V0

    float O[8][4];
#pragma unroll
    for (int n = 0; n < 8; ++n)
#pragma unroll
        for (int j = 0; j < 4; ++j) O[n][j] = 0.0f;
    float m_lo = -1e30f, m_hi = -1e30f, l_lo = 0.0f, l_hi = 0.0f;

    const int rlo = qt * 128 + w * 16 + g;
    const int nkt = 2 * qt + 2;

    for (int kt = 0; kt < nkt; ++kt) {
        if (kt + 1 < nkt) { issueKV(kt + 1, (kt + 1) & 1); cp_wait<1>(); }
        else cp_wait<0>();
        __syncthreads();
        const float* Ks = sm + 9216 + (kt & 1) * 4608;
        const float* Vs = sm + 18432 + (kt & 1) * 4608;

        // S = Q K^T (16x64 per warp)
        float Sa[8][4];
#pragma unroll
        for (int n = 0; n < 8; ++n)
#pragma unroll
            for (int j = 0; j < 4; ++j) Sa[n][j] = 0.0f;

#pragma unroll
        for (int s = 0; s < 8; ++s) {
            const float2 qlo = *(const float2*)&Qs[(w * 16 + g) * 72 + s * 8 + 2 * t4];
            const float2 qhi = *(const float2*)&Qs[(w * 16 + g + 8) * 72 + s * 8 + 2 * t4];
            const uint32_t a0 = __float_as_uint(qlo.x);
            const uint32_t a1 = __float_as_uint(qhi.x);
            const uint32_t a2 = __float_as_uint(qlo.y);
            const uint32_t a3 = __float_as_uint(qhi.y);
#pragma unroll
            for (int n = 0; n < 8; ++n) {
                const float2 kk = *(const float2*)&Ks[(n * 8 + g) * 72 + s * 8 + 2 * t4];
                mma8(Sa[n], a0, a1, a2, a3,
                     __float_as_uint(kk.x), __float_as_uint(kk.y));
            }
        }

        // causal mask (only the last two kv tiles cross the diagonal)
        if (kt >= 2 * qt) {
#pragma unroll
            for (int n = 0; n < 8; ++n) {
                const int c = kt * 64 + n * 8 + t4 * 2;
                if (c > rlo) Sa[n][0] = -1e30f;
                if (c + 1 > rlo) Sa[n][1] = -1e30f;
                if (c > rlo + 8) Sa[n][2] = -1e30f;
                if (c + 1 > rlo + 8) Sa[n][3] = -1e30f;
            }
        }

        // online softmax (rows g, g+8; warp-local quad reduction)
        float mx_lo = -1e30f, mx_hi = -1e30f;
#pragma unroll
        for (int n = 0; n < 8; ++n) {
            mx_lo = fmaxf(mx_lo, fmaxf(Sa[n][0], Sa[n][1]));
            mx_hi = fmaxf(mx_hi, fmaxf(Sa[n][2], Sa[n][3]));
        }
        mx_lo = fmaxf(mx_lo, __shfl_xor_sync(0xffffffffu, mx_lo, 1));
        mx_lo = fmaxf(mx_lo, __shfl_xor_sync(0xffffffffu, mx_lo, 2));
        mx_hi = fmaxf(mx_hi, __shfl_xor_sync(0xffffffffu, mx_hi, 1));
        mx_hi = fmaxf(mx_hi, __shfl_xor_sync(0xffffffffu, mx_hi, 2));
        const float mn_lo = fmaxf(m_lo, mx_lo);
        const float mn_hi = fmaxf(m_hi, mx_hi);
        const float al_lo = __expf(m_lo - mn_lo);
        const float al_hi = __expf(m_hi - mn_hi);
        m_lo = mn_lo;
        m_hi = mn_hi;
        float rs_lo = 0.0f, rs_hi = 0.0f;
#pragma unroll
        for (int n = 0; n < 8; ++n) {
            Sa[n][0] = __expf(Sa[n][0] - mn_lo);
            Sa[n][1] = __expf(Sa[n][1] - mn_lo);
            Sa[n][2] = __expf(Sa[n][2] - mn_hi);
            Sa[n][3] = __expf(Sa[n][3] - mn_hi);
            rs_lo += Sa[n][0] + Sa[n][1];
            rs_hi += Sa[n][2] + Sa[n][3];
        }
        rs_lo += __shfl_xor_sync(0xffffffffu, rs_lo, 1);
        rs_lo += __shfl_xor_sync(0xffffffffu, rs_lo, 2);
        rs_hi += __shfl_xor_sync(0xffffffffu, rs_hi, 1);
        rs_hi += __shfl_xor_sync(0xffffffffu, rs_hi, 2);
        l_lo = l_lo * al_lo + rs_lo;
        l_hi = l_hi * al_hi + rs_hi;
#pragma unroll
        for (int n = 0; n < 8; ++n) {
            O[n][0] *= al_lo;
            O[n][1] *= al_lo;
            O[n][2] *= al_hi;
            O[n][3] *= al_hi;
        }

        // O += P V : c-frag (cols 2t4,2t4+1) -> a-frag (cols t4,t4+4) via shfl
        const int src = (lane & ~3) | (t4 >> 1);
        const int src2 = src + 2;
        const bool odd = (t4 & 1);
#pragma unroll
        for (int j = 0; j < 8; ++j) {
            float x0 = __shfl_sync(0xffffffffu, Sa[j][0], src);
            float x1 = __shfl_sync(0xffffffffu, Sa[j][1], src);
            float y0 = __shfl_sync(0xffffffffu, Sa[j][0], src2);
            float y1 = __shfl_sync(0xffffffffu, Sa[j][1], src2);
            const uint32_t pa0 = f2tf(odd ? x1 : x0);
            const uint32_t pa2 = f2tf(odd ? y1 : y0);
            x0 = __shfl_sync(0xffffffffu, Sa[j][2], src);
            x1 = __shfl_sync(0xffffffffu, Sa[j][3], src);
            y0 = __shfl_sync(0xffffffffu, Sa[j][2], src2);
            y1 = __shfl_sync(0xffffffffu, Sa[j][3], src2);
            const uint32_t pa1 = f2tf(odd ? x1 : x0);
            const uint32_t pa3 = f2tf(odd ? y1 : y0);
#pragma unroll
            for (int n = 0; n < 8; ++n) {
                const uint32_t b0 = __float_as_uint(Vs[(j * 8 + t4) * 72 + n * 8 + g]);
                const uint32_t b1 = __float_as_uint(Vs[(j * 8 + t4 + 4) * 72 + n * 8 + g]);
                mma8(O[n], pa0, pa1, pa2, pa3, b0, b1);
            }
        }
        __syncthreads();  // compute done before next issue overwrites this buf
    }

    // write y [B,T,C]: rounded + sigma-permuted (feeds proj GEMM fragments)
    const float inv_lo = 1.0f / l_lo;
    const float inv_hi = 1.0f / l_hi;
    float* y0 = g_y + (size_t)(b * TT + rlo) * CC;
    float* y1 = g_y + (size_t)(b * TT + rlo + 8) * CC;
#pragma unroll
    for (int n = 0; n < 8; ++n) {
        const int cb = h * HD + n * 8;
        const int c0 = cb + sig8(2 * t4);
        const int c1 = cb + sig8(2 * t4 + 1);
        y0[c0] = f2tff(O[n][0] * inv_lo);
        y0[c1] = f2tff(O[n][1] * inv_lo);
        y1[c0] = f2tff(O[n][2] * inv_hi);
        y1[c1] = f2tff(O[n][3] * inv_hi);
    }
}

// ---------------------------------------------------------------------------
extern "C" void kernel_launch(void* const* d_in, const int* in_sizes, int n_in,
                              void* d_out, int out_size)
{
    (void)in_sizes; (void)n_in; (void)out_size;
    const float* x      = (const float*)d_in[0];
    const float* W_attn = (const float*)d_in[1];
    const float* b_attn = (const float*)d_in[2];
    const float* W_proj = (const float*)d_in[3];
    const float* b_proj = (const float*)d_in[4];
    float* out = (float*)d_out;

    cudaFuncSetAttribute(gemm_mma<0, 3072>,
                         cudaFuncAttributeMaxDynamicSharedMemorySize, 81920);
    cudaFuncSetAttribute(gemm_mma<1, 1024>,
                         cudaFuncAttributeMaxDynamicSharedMemorySize, 81920);
    cudaFuncSetAttribute(attn_mma,
                         cudaFuncAttributeMaxDynamicSharedMemorySize, 110592);

    // 0) round/transpose/permute inputs
    prep_x<<<(BB * TT * CC) / 1024, 1024>>>(x);
    prep_w<<<dim3(3072 / 32, 1024 / 32), dim3(32, 8)>>>(W_attn, 3072, 0);
    prep_w<<<dim3(1024 / 32, 1024 / 32), dim3(32, 8)>>>(W_proj, 1024, 1);

    // 1) QKV GEMM + bias -> q/k/v
    gemm_mma<0, 3072><<<dim3(24, 32), 256, 81920>>>(b_attn, nullptr);

    // 2) causal flash attention -> g_y
    attn_mma<<<dim3(16, HH, BB), 256, 110592>>>();

    // 3) output projection + bias -> out
    gemm_mma<1, 1024><<<dim3(8, 32), 256, 81920>>>(b_proj, out);
}

// round 8
// speedup vs baseline: 5.4133x; 1.7798x over previous
#include <cuda_runtime.h>
#include <cuda_fp16.h>
#include <cstdint>

// Problem constants
#define BB 2
#define TT 2048
#define CC 1024
#define HH 16
#define HD 64

// Scratch (no cudaMalloc). All fp16 where consumed by mma.
// g_q/g_k/g_v: [B,H,T,64] half (q pre-scaled by 0.125)
// g_y:  [B,T,C] half (attention out, feeds proj GEMM)
// g_xr: x as half; g_war/g_wpr: W transposed [N][K] half
__device__ __align__(256) __half g_q[BB * HH * TT * HD];
__device__ __align__(256) __half g_k[BB * HH * TT * HD];
__device__ __align__(256) __half g_v[BB * HH * TT * HD];
__device__ __align__(256) __half g_y[BB * TT * CC];
__device__ __align__(256) __half g_xr[BB * TT * CC];
__device__ __align__(256) __half g_war[3 * CC * CC];
__device__ __align__(256) __half g_wpr[CC * CC];

// ---------------------------------------------------------------------------
// helpers
// ---------------------------------------------------------------------------
__device__ __forceinline__ uint32_t packh2(float lo, float hi) {
    __half2 h = __floats2half2_rn(lo, hi);
    return *reinterpret_cast<uint32_t*>(&h);
}

__device__ __forceinline__ void mma16(float* c, uint32_t a0, uint32_t a1,
                                      uint32_t a2, uint32_t a3,
                                      uint32_t b0, uint32_t b1) {
    asm volatile(
        "mma.sync.aligned.m16n8k16.row.col.f32.f16.f16.f32 "
        "{%0,%1,%2,%3}, {%4,%5,%6,%7}, {%8,%9}, {%0,%1,%2,%3};"
        : "+f"(c[0]), "+f"(c[1]), "+f"(c[2]), "+f"(c[3])
        : "r"(a0), "r"(a1), "r"(a2), "r"(a3), "r"(b0), "r"(b1));
}

__device__ __forceinline__ void ldm4(uint32_t& r0, uint32_t& r1, uint32_t& r2,
                                     uint32_t& r3, uint32_t a) {
    asm volatile("ldmatrix.sync.aligned.m8n8.x4.shared.b16 {%0,%1,%2,%3}, [%4];"
                 : "=r"(r0), "=r"(r1), "=r"(r2), "=r"(r3) : "r"(a));
}
__device__ __forceinline__ void ldm4t(uint32_t& r0, uint32_t& r1, uint32_t& r2,
                                      uint32_t& r3, uint32_t a) {
    asm volatile("ldmatrix.sync.aligned.m8n8.x4.trans.shared.b16 {%0,%1,%2,%3}, [%4];"
                 : "=r"(r0), "=r"(r1), "=r"(r2), "=r"(r3) : "r"(a));
}

__device__ __forceinline__ void cpa16(uint32_t dst, const void* src) {
    asm volatile("cp.async.cg.shared.global [%0], [%1], 16;" :: "r"(dst), "l"(src));
}
__device__ __forceinline__ void cp_commit() {
    asm volatile("cp.async.commit_group;");
}
template <int N>
__device__ __forceinline__ void cp_wait() {
    asm volatile("cp.async.wait_group %0;" :: "n"(N));
}

__device__ __forceinline__ uint32_t s2u(const void* p) {
    return (uint32_t)__cvta_generic_to_shared(p);
}

// padded row stride: 72 halves = 144 B (conflict-free ldmatrix phases)
#define RS 144

// ---------------------------------------------------------------------------
// prep kernels
// ---------------------------------------------------------------------------
__global__ void prep_x(const float* __restrict__ x) {
    const int i = blockIdx.x * blockDim.x + threadIdx.x;
    g_xr[i] = __float2half(x[i]);
}

// W [1024 x Nc] row-major f32 -> Wt [Nc x 1024] half
__global__ void prep_w(const float* __restrict__ W, int Nc, int which) {
    __shared__ float t[32][33];
    __half* Wt = which ? g_wpr : g_war;
    const int n0 = blockIdx.x * 32, k0 = blockIdx.y * 32;
    const int tx = threadIdx.x, ty0 = threadIdx.y;
#pragma unroll
    for (int i = 0; i < 4; ++i) {
        const int ty = ty0 + i * 8;
        t[ty][tx] = W[(size_t)(k0 + ty) * Nc + n0 + tx];
    }
    __syncthreads();
#pragma unroll
    for (int i = 0; i < 4; ++i) {
        const int ty = ty0 + i * 8;
        Wt[(size_t)(n0 + ty) * 1024 + k0 + tx] = __float2half(t[tx][ty]);
    }
}

// ---------------------------------------------------------------------------
// GEMM: C[M,N] = A[M,1024] @ W[1024,N] + bias  (fp16 mma m16n8k16, fp32 acc)
//   MODE 0: A=g_xr, Wt=g_war, scatter half q/k/v (q scaled 0.125)
//   MODE 1: A=g_y,  Wt=g_wpr, out full fp32
// BM=BN=128, BK=32, 256 threads (8 warps 4m x 2n, warp tile 32x64)
// smem per stage: A 128xRS + B 128xRS = 36864 B; 2 stages = 73728 B
// ---------------------------------------------------------------------------
template <int MODE, int NW>
__global__ __launch_bounds__(256, 2) void gemm_mma(const float* __restrict__ bias,
                                                   float* __restrict__ out)
{
    extern __shared__ __align__(16) char smem[];
    const uint32_t sb = s2u(smem);

    const __half* A  = (MODE == 0) ? g_xr : g_y;
    const __half* Wt = (MODE == 0) ? g_war : g_wpr;

    const int tid = threadIdx.x;
    const int lane = tid & 31;
    const int g = lane >> 2, t4 = lane & 3;
    const int w = tid >> 5;
    const int wm = w & 3, wn = w >> 2;
    const int row0 = blockIdx.y * 128, col0 = blockIdx.x * 128;

    auto issue = [&](int kt, int s) {
        const uint32_t a_s = sb + s * 18432;
        const uint32_t b_s = sb + 36864 + s * 18432;
#pragma unroll
        for (int r = 0; r < 2; ++r) {
            const int idx = tid + r * 256;
            const int m = idx >> 2, c = idx & 3;  // 4 x 16B chunks per 64B row
            cpa16(a_s + (uint32_t)(m * RS + c * 16),
                  A + (size_t)(row0 + m) * 1024 + kt * 32 + c * 8);
            cpa16(b_s + (uint32_t)(m * RS + c * 16),
                  Wt + (size_t)(col0 + m) * 1024 + kt * 32 + c * 8);
        }
        cp_commit();
    };

    float acc[2][8][4];
#pragma unroll
    for (int mi = 0; mi < 2; ++mi)
#pragma unroll
        for (int ni = 0; ni < 8; ++ni)
#pragma unroll
            for (int j = 0; j < 4; ++j) acc[mi][ni][j] = 0.0f;

    // ldmatrix lane addressing (bytes)
    const int arow = wm * 32 + (lane & 15);        // + mi*16
    const uint32_t asel = (uint32_t)((lane >> 4) * 16);
    const int brow = wn * 64 + (lane & 7) + ((lane >> 4) << 3);  // + np*16
    const uint32_t bsel = (uint32_t)(((lane >> 3) & 1) * 16);

    issue(0, 0);
    for (int kt = 0; kt < 32; ++kt) {
        const int s = kt & 1;
        if (kt < 31) { issue(kt + 1, s ^ 1); cp_wait<1>(); }
        else cp_wait<0>();
        __syncthreads();
        const uint32_t a_s = sb + s * 18432;
        const uint32_t b_s = sb + 36864 + s * 18432;
#pragma unroll
        for (int ks = 0; ks < 2; ++ks) {  // two k16 steps
            uint32_t a[2][4];
#pragma unroll
            for (int mi = 0; mi < 2; ++mi)
                ldm4(a[mi][0], a[mi][1], a[mi][2], a[mi][3],
                     a_s + (uint32_t)((arow + mi * 16) * RS + ks * 32) + asel);
            uint32_t b[8][2];
#pragma unroll
            for (int np = 0; np < 4; ++np)
                ldm4(b[2 * np][0], b[2 * np][1], b[2 * np + 1][0], b[2 * np + 1][1],
                     b_s + (uint32_t)((brow + np * 16) * RS + ks * 32) + bsel);
#pragma unroll
            for (int ni = 0; ni < 8; ++ni) {
                mma16(acc[0][ni], a[0][0], a[0][1], a[0][2], a[0][3], b[ni][0], b[ni][1]);
                mma16(acc[1][ni], a[1][0], a[1][1], a[1][2], a[1][3], b[ni][0], b[ni][1]);
            }
        }
        __syncthreads();
    }

    // Epilogue: c-frag rows (g, g+8), cols (2t4, 2t4+1)
#pragma unroll
    for (int mi = 0; mi < 2; ++mi) {
        const int r_lo = row0 + wm * 32 + mi * 16 + g;
#pragma unroll
        for (int ni = 0; ni < 8; ++ni) {
            const int c = col0 + wn * 64 + ni * 8 + t4 * 2;
            const float v00 = acc[mi][ni][0] + bias[c];
            const float v01 = acc[mi][ni][1] + bias[c + 1];
            const float v10 = acc[mi][ni][2] + bias[c];
            const float v11 = acc[mi][ni][3] + bias[c + 1];
            if (MODE == 0) {
                const int which = c >> 10;
                const int rem = c & 1023;
                const int hh = rem >> 6;
                const int dl = rem & 63;  // even, pair inside head
                const int bb0 = r_lo >> 11, t0 = r_lo & 2047;
                const int bb1 = (r_lo + 8) >> 11, t1 = (r_lo + 8) & 2047;
                __half* dst = (which == 0) ? g_q : (which == 1 ? g_k : g_v);
                const float sc = (which == 0) ? 0.125f : 1.0f;
                *(__half2*)(dst + ((size_t)(bb0 * HH + hh) * TT + t0) * HD + dl) =
                    __floats2half2_rn(v00 * sc, v01 * sc);
                *(__half2*)(dst + ((size_t)(bb1 * HH + hh) * TT + t1) * HD + dl) =
                    __floats2half2_rn(v10 * sc, v11 * sc);
            } else {
                float2 lo, hi;
                lo.x = v00; lo.y = v01;
                hi.x = v10; hi.y = v11;
                *(float2*)(out + (size_t)r_lo * NW + c) = lo;
                *(float2*)(out + (size_t)(r_lo + 8) * NW + c) = hi;
            }
        }
    }
}

// ---------------------------------------------------------------------------
// Flash attention (causal), fp16 mma + ldmatrix, cp.async double-buffered K/V.
// One block = 128 q rows of one (b,h); 8 warps m-split (warp-local softmax).
// smem: Qs 128xRS (18432) + 2x Ks 64xRS (9216) + 2x Vs 64xRS = 55296 B
// ---------------------------------------------------------------------------
__global__ __launch_bounds__(256, 2) void attn_mma()
{
    extern __shared__ __align__(16) char smc[];
    const uint32_t sb = s2u(smc);
    const uint32_t sQ = sb;
    const uint32_t sK0 = sb + 18432;
    const uint32_t sV0 = sb + 36864;

    const int tid = threadIdx.x;
    const int lane = tid & 31;
    const int w = tid >> 5;
    const int g = lane >> 2, t4 = lane & 3;
    const int qt = 15 - (int)blockIdx.x;  // heavy tiles first
    const int h = blockIdx.y, b = blockIdx.z;

    const size_t ho = (size_t)(b * HH + h) * TT * HD;
    const __half* qb = g_q + ho;
    const __half* kb = g_k + ho;
    const __half* vb = g_v + ho;

    // Q tile: 128 rows x 64 halves = 8 x 16B chunks per row
#pragma unroll
    for (int r = 0; r < 4; ++r) {
        const int idx = tid + r * 256;
        const int m = idx >> 3, c = idx & 7;
        cpa16(sQ + (uint32_t)(m * RS + c * 16),
              qb + (size_t)(qt * 128 + m) * HD + c * 8);
    }
    auto issueKV = [&](int kt, int buf) {
#pragma unroll
        for (int r = 0; r < 2; ++r) {
            const int idx = tid + r * 256;
            const int m = idx >> 3, c = idx & 7;
            const uint32_t off = (uint32_t)(m * RS + c * 16) + buf * 9216u;
            cpa16(sK0 + off, kb + (size_t)(kt * 64 + m) * HD + c * 8);
            cpa16(sV0 + off, vb + (size_t)(kt * 64 + m) * HD + c * 8);
        }
        cp_commit();
    };
    issueKV(0, 0);  // group 0 = Q + K0 + V0

    float O[8][4];
#pragma unroll
    for (int n = 0; n < 8; ++n)
#pragma unroll
        for (int j = 0; j < 4; ++j) O[n][j] = 0.0f;
    float m_lo = -1e30f, m_hi = -1e30f, l_lo = 0.0f, l_hi = 0.0f;

    const int rlo = qt * 128 + w * 16 + g;
    const int nkt = 2 * qt + 2;

    // ldmatrix lane addressing
    const int qrow = w * 16 + (lane & 15);
    const uint32_t qsel = (uint32_t)((lane >> 4) * 16);
    const int krow = (lane & 7) + ((lane >> 4) << 3);   // + np*16
    const uint32_t ksel = (uint32_t)(((lane >> 3) & 1) * 16);
    const int vrow = (lane & 15);                        // + 16*s
    const uint32_t vsel = (uint32_t)(((lane >> 4) & 1) * 16);

    uint32_t aq[4][4];  // Q fragments, hoisted across kv loop

    for (int kt = 0; kt < nkt; ++kt) {
        if (kt + 1 < nkt) { issueKV(kt + 1, (kt + 1) & 1); cp_wait<1>(); }
        else cp_wait<0>();
        __syncthreads();
        if (kt == 0) {
#pragma unroll
            for (int s = 0; s < 4; ++s)
                ldm4(aq[s][0], aq[s][1], aq[s][2], aq[s][3],
                     sQ + (uint32_t)(qrow * RS + s * 32) + qsel);
        }
        const uint32_t Ks = sK0 + (kt & 1) * 9216u;
        const uint32_t Vs = sV0 + (kt & 1) * 9216u;

        // S = Q K^T  (warp: 16 rows x 64 kv cols)
        float Sa[8][4];
#pragma unroll
        for (int n = 0; n < 8; ++n)
#pragma unroll
            for (int j = 0; j < 4; ++j) Sa[n][j] = 0.0f;

#pragma unroll
        for (int s = 0; s < 4; ++s) {
            uint32_t bk[8][2];
#pragma unroll
            for (int np = 0; np < 4; ++np)
                ldm4(bk[2 * np][0], bk[2 * np][1], bk[2 * np + 1][0], bk[2 * np + 1][1],
                     Ks + (uint32_t)((krow + np * 16) * RS + s * 32) + ksel);
#pragma unroll
            for (int n = 0; n < 8; ++n)
                mma16(Sa[n], aq[s][0], aq[s][1], aq[s][2], aq[s][3],
                      bk[n][0], bk[n][1]);
        }

        // causal mask (only the last two kv tiles cross the diagonal)
        if (kt >= 2 * qt) {
#pragma unroll
            for (int n = 0; n < 8; ++n) {
                const int c = kt * 64 + n * 8 + t4 * 2;
                if (c > rlo) Sa[n][0] = -1e30f;
                if (c + 1 > rlo) Sa[n][1] = -1e30f;
                if (c > rlo + 8) Sa[n][2] = -1e30f;
                if (c + 1 > rlo + 8) Sa[n][3] = -1e30f;
            }
        }

        // online softmax (rows g, g+8; quad reduction)
        float mx_lo = -1e30f, mx_hi = -1e30f;
#pragma unroll
        for (int n = 0; n < 8; ++n) {
            mx_lo = fmaxf(mx_lo, fmaxf(Sa[n][0], Sa[n][1]));
            mx_hi = fmaxf(mx_hi, fmaxf(Sa[n][2], Sa[n][3]));
        }
        mx_lo = fmaxf(mx_lo, __shfl_xor_sync(0xffffffffu, mx_lo, 1));
        mx_lo = fmaxf(mx_lo, __shfl_xor_sync(0xffffffffu, mx_lo, 2));
        mx_hi = fmaxf(mx_hi, __shfl_xor_sync(0xffffffffu, mx_hi, 1));
        mx_hi = fmaxf(mx_hi, __shfl_xor_sync(0xffffffffu, mx_hi, 2));
        const float mn_lo = fmaxf(m_lo, mx_lo);
        const float mn_hi = fmaxf(m_hi, mx_hi);
        const float al_lo = __expf(m_lo - mn_lo);
        const float al_hi = __expf(m_hi - mn_hi);
        m_lo = mn_lo;
        m_hi = mn_hi;
        float rs_lo = 0.0f, rs_hi = 0.0f;
#pragma unroll
        for (int n = 0; n < 8; ++n) {
            Sa[n][0] = __expf(Sa[n][0] - mn_lo);
            Sa[n][1] = __expf(Sa[n][1] - mn_lo);
            Sa[n][2] = __expf(Sa[n][2] - mn_hi);
            Sa[n][3] = __expf(Sa[n][3] - mn_hi);
            rs_lo += Sa[n][0] + Sa[n][1];
            rs_hi += Sa[n][2] + Sa[n][3];
        }
        rs_lo += __shfl_xor_sync(0xffffffffu, rs_lo, 1);
        rs_lo += __shfl_xor_sync(0xffffffffu, rs_lo, 2);
        rs_hi += __shfl_xor_sync(0xffffffffu, rs_hi, 1);
        rs_hi += __shfl_xor_sync(0xffffffffu, rs_hi, 2);
        l_lo = l_lo * al_lo + rs_lo;
        l_hi = l_hi * al_hi + rs_hi;
#pragma unroll
        for (int n = 0; n < 8; ++n) {
            O[n][0] *= al_lo;
            O[n][1] *= al_lo;
            O[n][2] *= al_hi;
            O[n][3] *= al_hi;
        }

        // O += P V : P a-frags come straight from S c-frag pairs (fp16 pack)
#pragma unroll
        for (int s = 0; s < 4; ++s) {
            const uint32_t pa0 = packh2(Sa[2 * s][0], Sa[2 * s][1]);
            const uint32_t pa1 = packh2(Sa[2 * s][2], Sa[2 * s][3]);
            const uint32_t pa2 = packh2(Sa[2 * s + 1][0], Sa[2 * s + 1][1]);
            const uint32_t pa3 = packh2(Sa[2 * s + 1][2], Sa[2 * s + 1][3]);
            uint32_t bv[8][2];
#pragma unroll
            for (int vp = 0; vp < 4; ++vp)
                ldm4t(bv[2 * vp][0], bv[2 * vp][1], bv[2 * vp + 1][0], bv[2 * vp + 1][1],
                      Vs + (uint32_t)((16 * s + vrow) * RS + vp * 32) + vsel);
#pragma unroll
            for (int n = 0; n < 8; ++n)
                mma16(O[n], pa0, pa1, pa2, pa3, bv[n][0], bv[n][1]);
        }
        __syncthreads();  // compute done before next issue overwrites this buf
    }

    // write y [B,T,C] half
    const float inv_lo = 1.0f / l_lo;
    const float inv_hi = 1.0f / l_hi;
    __half* y0 = g_y + (size_t)(b * TT + rlo) * CC;
    __half* y1 = g_y + (size_t)(b * TT + rlo + 8) * CC;
#pragma unroll
    for (int n = 0; n < 8; ++n) {
        const int c = h * HD + n * 8 + t4 * 2;
        *(__half2*)(y0 + c) = __floats2half2_rn(O[n][0] * inv_lo, O[n][1] * inv_lo);
        *(__half2*)(y1 + c) = __floats2half2_rn(O[n][2] * inv_hi, O[n][3] * inv_hi);
    }
}

// ---------------------------------------------------------------------------
extern "C" void kernel_launch(void* const* d_in, const int* in_sizes, int n_in,
                              void* d_out, int out_size)
{
    (void)in_sizes; (void)n_in; (void)out_size;
    const float* x      = (const float*)d_in[0];
    const float* W_attn = (const float*)d_in[1];
    const float* b_attn = (const float*)d_in[2];
    const float* W_proj = (const float*)d_in[3];
    const float* b_proj = (const float*)d_in[4];
    float* out = (float*)d_out;

    const int smem_gemm = 2 * 36864;  // 73728 B
    const int smem_attn = 55296;
    cudaFuncSetAttribute(gemm_mma<0, 3072>,
                         cudaFuncAttributeMaxDynamicSharedMemorySize, smem_gemm);
    cudaFuncSetAttribute(gemm_mma<1, 1024>,
                         cudaFuncAttributeMaxDynamicSharedMemorySize, smem_gemm);
    cudaFuncSetAttribute(attn_mma,
                         cudaFuncAttributeMaxDynamicSharedMemorySize, smem_attn);

    // 0) convert inputs to half (+ transpose W)
    prep_x<<<(BB * TT * CC) / 256, 256>>>(x);
    prep_w<<<dim3(3072 / 32, 1024 / 32), dim3(32, 8)>>>(W_attn, 3072, 0);
    prep_w<<<dim3(1024 / 32, 1024 / 32), dim3(32, 8)>>>(W_proj, 1024, 1);

    // 1) QKV GEMM + bias -> q/k/v (half)
    gemm_mma<0, 3072><<<dim3(24, 32), 256, smem_gemm>>>(b_attn, nullptr);

    // 2) causal flash attention -> g_y (half)
    attn_mma<<<dim3(16, HH, BB), 256, smem_attn>>>();

    // 3) output projection + bias -> out (f32)
    gemm_mma<1, 1024><<<dim3(8, 32), 256, smem_gemm>>>(b_proj, out);
}

// round 10
// speedup vs baseline: 6.5064x; 1.2019x over previous
#include <cuda_runtime.h>
#include <cuda_fp16.h>
#include <cstdint>

// Problem constants
#define BB 2
#define TT 2048
#define CC 1024
#define HH 16
#define HD 64

// Scratch (no cudaMalloc). All fp16 where consumed by mma.
__device__ __align__(256) __half g_q[BB * HH * TT * HD];
__device__ __align__(256) __half g_k[BB * HH * TT * HD];
__device__ __align__(256) __half g_v[BB * HH * TT * HD];
__device__ __align__(256) __half g_y[BB * TT * CC];
__device__ __align__(256) __half g_xr[BB * TT * CC];
__device__ __align__(256) __half g_war[3 * CC * CC];
__device__ __align__(256) __half g_wpr[CC * CC];

// ---------------------------------------------------------------------------
// helpers
// ---------------------------------------------------------------------------
__device__ __forceinline__ uint32_t packh2(float lo, float hi) {
    __half2 h = __floats2half2_rn(lo, hi);
    return *reinterpret_cast<uint32_t*>(&h);
}

__device__ __forceinline__ void mma16(float* c, uint32_t a0, uint32_t a1,
                                      uint32_t a2, uint32_t a3,
                                      uint32_t b0, uint32_t b1) {
    asm volatile(
        "mma.sync.aligned.m16n8k16.row.col.f32.f16.f16.f32 "
        "{%0,%1,%2,%3}, {%4,%5,%6,%7}, {%8,%9}, {%0,%1,%2,%3};"
        : "+f"(c[0]), "+f"(c[1]), "+f"(c[2]), "+f"(c[3])
        : "r"(a0), "r"(a1), "r"(a2), "r"(a3), "r"(b0), "r"(b1));
}

__device__ __forceinline__ void ldm4(uint32_t& r0, uint32_t& r1, uint32_t& r2,
                                     uint32_t& r3, uint32_t a) {
    asm volatile("ldmatrix.sync.aligned.m8n8.x4.shared.b16 {%0,%1,%2,%3}, [%4];"
                 : "=r"(r0), "=r"(r1), "=r"(r2), "=r"(r3) : "r"(a));
}
__device__ __forceinline__ void ldm4t(uint32_t& r0, uint32_t& r1, uint32_t& r2,
                                      uint32_t& r3, uint32_t a) {
    asm volatile("ldmatrix.sync.aligned.m8n8.x4.trans.shared.b16 {%0,%1,%2,%3}, [%4];"
                 : "=r"(r0), "=r"(r1), "=r"(r2), "=r"(r3) : "r"(a));
}

__device__ __forceinline__ void cpa16(uint32_t dst, const void* src) {
    asm volatile("cp.async.cg.shared.global [%0], [%1], 16;" :: "r"(dst), "l"(src));
}
__device__ __forceinline__ void cp_commit() {
    asm volatile("cp.async.commit_group;");
}
template <int N>
__device__ __forceinline__ void cp_wait() {
    asm volatile("cp.async.wait_group %0;" :: "n"(N));
}

__device__ __forceinline__ uint32_t s2u(const void* p) {
    return (uint32_t)__cvta_generic_to_shared(p);
}

// XOR swizzle: 128B rows of 8 x 16B chunks; chunk c of row m lives at c^(m&7)
__device__ __forceinline__ uint32_t swz(int m, int c) {
    return (uint32_t)(m * 128 + ((c ^ (m & 7)) << 4));
}

// ---------------------------------------------------------------------------
// prep kernels
// ---------------------------------------------------------------------------
__global__ void prep_x(const float* __restrict__ x) {
    const int i = blockIdx.x * blockDim.x + threadIdx.x;
    const float4 v = *(const float4*)(x + i * 4);
    __half2* p = (__half2*)(g_xr + i * 4);
    p[0] = __floats2half2_rn(v.x, v.y);
    p[1] = __floats2half2_rn(v.z, v.w);
}

// W [1024 x Nc] row-major f32 -> Wt [Nc x 1024] half
__global__ void prep_w(const float* __restrict__ W, int Nc, int which) {
    __shared__ float t[32][33];
    __half* Wt = which ? g_wpr : g_war;
    const int n0 = blockIdx.x * 32, k0 = blockIdx.y * 32;
    const int tx = threadIdx.x, ty0 = threadIdx.y;
#pragma unroll
    for (int i = 0; i < 4; ++i) {
        const int ty = ty0 + i * 8;
        t[ty][tx] = W[(size_t)(k0 + ty) * Nc + n0 + tx];
    }
    __syncthreads();
#pragma unroll
    for (int i = 0; i < 4; ++i) {
        const int ty = ty0 + i * 8;
        Wt[(size_t)(n0 + ty) * 1024 + k0 + tx] = __float2half(t[tx][ty]);
    }
}

// ---------------------------------------------------------------------------
// GEMM: C[M,N] = A[M,1024] @ W[1024,N] + bias  (fp16 mma m16n8k16, fp32 acc)
//   MODE 0: A=g_xr, Wt=g_war, scatter half q/k/v (q scaled 0.125)
//   MODE 1: A=g_y,  Wt=g_wpr, out full fp32
// BM=BN=128, BK=64, 256 threads (8 warps 4m x 2n, warp tile 32x64)
// 3-stage cp.async ring, ONE __syncthreads per k-tile, swizzled 128B rows.
// smem: 3 stages x (A 16384 + B 16384) = 98304 B
// ---------------------------------------------------------------------------
template <int MODE, int NW>
__global__ __launch_bounds__(256, 2) void gemm_mma(const float* __restrict__ bias,
                                                   float* __restrict__ out)
{
    extern __shared__ __align__(16) char smem[];
    const uint32_t sb = s2u(smem);

    const __half* A  = (MODE == 0) ? g_xr : g_y;
    const __half* Wt = (MODE == 0) ? g_war : g_wpr;

    const int tid = threadIdx.x;
    const int lane = tid & 31;
    const int g = lane >> 2, t4 = lane & 3;
    const int w = tid >> 5;
    const int wm = w & 3, wn = w >> 2;
    const int row0 = blockIdx.y * 128, col0 = blockIdx.x * 128;

    auto issue = [&](int kt, int st) {
        const uint32_t base = sb + st * 32768;
#pragma unroll
        for (int r = 0; r < 4; ++r) {
            const int idx = tid + r * 256;
            const int m = idx >> 3, c = idx & 7;
            const uint32_t o = swz(m, c);
            cpa16(base + o, A + (size_t)(row0 + m) * 1024 + kt * 64 + c * 8);
            cpa16(base + 16384 + o, Wt + (size_t)(col0 + m) * 1024 + kt * 64 + c * 8);
        }
        cp_commit();
    };

    float acc[2][8][4];
#pragma unroll
    for (int mi = 0; mi < 2; ++mi)
#pragma unroll
        for (int ni = 0; ni < 8; ++ni)
#pragma unroll
            for (int j = 0; j < 4; ++j) acc[mi][ni][j] = 0.0f;

    // ldmatrix lane row/chunk decomposition
    const int ar = wm * 32 + (lane & 15);                      // + mi*16
    const int abit = lane >> 4;                                // chunk low bit
    const int br = wn * 64 + (lane & 7) + ((lane >> 4) << 3);  // + np*16
    const int bbit = (lane >> 3) & 1;

    issue(0, 0);
    issue(1, 1);
    for (int kt = 0; kt < 16; ++kt) {
        if (kt + 1 < 16) cp_wait<1>(); else cp_wait<0>();
        __syncthreads();
        if (kt + 2 < 16) issue(kt + 2, (kt + 2) % 3);
        const uint32_t a_s = sb + (kt % 3) * 32768;
        const uint32_t b_s = a_s + 16384;
#pragma unroll
        for (int ks = 0; ks < 4; ++ks) {
            uint32_t a[2][4];
#pragma unroll
            for (int mi = 0; mi < 2; ++mi) {
                const int r = ar + mi * 16;
                ldm4(a[mi][0], a[mi][1], a[mi][2], a[mi][3],
                     a_s + swz(r, 2 * ks + abit));
            }
            uint32_t b[8][2];
#pragma unroll
            for (int np = 0; np < 4; ++np) {
                const int r = br + np * 16;
                ldm4(b[2 * np][0], b[2 * np][1], b[2 * np + 1][0], b[2 * np + 1][1],
                     b_s + swz(r, 2 * ks + bbit));
            }
#pragma unroll
            for (int ni = 0; ni < 8; ++ni) {
                mma16(acc[0][ni], a[0][0], a[0][1], a[0][2], a[0][3], b[ni][0], b[ni][1]);
                mma16(acc[1][ni], a[1][0], a[1][1], a[1][2], a[1][3], b[ni][0], b[ni][1]);
            }
        }
    }

    // Epilogue: c-frag rows (g, g+8), cols (2t4, 2t4+1)
#pragma unroll
    for (int mi = 0; mi < 2; ++mi) {
        const int r_lo = row0 + wm * 32 + mi * 16 + g;
#pragma unroll
        for (int ni = 0; ni < 8; ++ni) {
            const int c = col0 + wn * 64 + ni * 8 + t4 * 2;
            const float v00 = acc[mi][ni][0] + bias[c];
            const float v01 = acc[mi][ni][1] + bias[c + 1];
            const float v10 = acc[mi][ni][2] + bias[c];
            const float v11 = acc[mi][ni][3] + bias[c + 1];
            if (MODE == 0) {
                const int which = c >> 10;
                const int rem = c & 1023;
                const int hh = rem >> 6;
                const int dl = rem & 63;  // even, pair inside head
                const int bb0 = r_lo >> 11, t0 = r_lo & 2047;
                const int bb1 = (r_lo + 8) >> 11, t1 = (r_lo + 8) & 2047;
                __half* dst = (which == 0) ? g_q : (which == 1 ? g_k : g_v);
                const float sc = (which == 0) ? 0.125f : 1.0f;
                *(__half2*)(dst + ((size_t)(bb0 * HH + hh) * TT + t0) * HD + dl) =
                    __floats2half2_rn(v00 * sc, v01 * sc);
                *(__half2*)(dst + ((size_t)(bb1 * HH + hh) * TT + t1) * HD + dl) =
                    __floats2half2_rn(v10 * sc, v11 * sc);
            } else {
                float2 lo, hi;
                lo.x = v00; lo.y = v01;
                hi.x = v10; hi.y = v11;
                *(float2*)(out + (size_t)r_lo * NW + c) = lo;
                *(float2*)(out + (size_t)(r_lo + 8) * NW + c) = hi;
            }
        }
    }
}

// ---------------------------------------------------------------------------
// Flash attention (causal), fp16 mma + ldmatrix, 3-stage cp.async K/V ring,
// one __syncthreads per kv tile. One block = 128 q rows of one (b,h).
// smem: Q 16384 + 3 x (K 8192 + V 8192) = 65536 B  (swizzled 128B rows)
// ---------------------------------------------------------------------------
__global__ __launch_bounds__(256, 2) void attn_mma()
{
    extern __shared__ __align__(16) char smc[];
    const uint32_t sb = s2u(smc);
    const uint32_t sQ = sb;

    const int tid = threadIdx.x;
    const int lane = tid & 31;
    const int w = tid >> 5;
    const int g = lane >> 2, t4 = lane & 3;
    const int qt = 15 - (int)blockIdx.x;  // heavy tiles first
    const int h = blockIdx.y, b = blockIdx.z;

    const size_t ho = (size_t)(b * HH + h) * TT * HD;
    const __half* qb = g_q + ho;
    const __half* kb = g_k + ho;
    const __half* vb = g_v + ho;

    auto issueKV = [&](int kt, int st) {
        const uint32_t base = sb + 16384 + st * 16384;
#pragma unroll
        for (int r = 0; r < 2; ++r) {
            const int idx = tid + r * 256;
            const int m = idx >> 3, c = idx & 7;
            const uint32_t o = swz(m, c);
            cpa16(base + o, kb + (size_t)(kt * 64 + m) * HD + c * 8);
            cpa16(base + 8192 + o, vb + (size_t)(kt * 64 + m) * HD + c * 8);
        }
        cp_commit();
    };

    // Q tile + first KV in group 0
#pragma unroll
    for (int r = 0; r < 4; ++r) {
        const int idx = tid + r * 256;
        const int m = idx >> 3, c = idx & 7;
        cpa16(sQ + swz(m, c), qb + (size_t)(qt * 128 + m) * HD + c * 8);
    }
    issueKV(0, 0);

    const int nkt = 2 * qt + 2;
    if (nkt > 1) issueKV(1, 1);

    float O[8][4];
#pragma unroll
    for (int n = 0; n < 8; ++n)
#pragma unroll
        for (int j = 0; j < 4; ++j) O[n][j] = 0.0f;
    float m_lo = -1e30f, m_hi = -1e30f, l_lo = 0.0f, l_hi = 0.0f;

    const int rlo = qt * 128 + w * 16 + g;

    // ldmatrix lane row/chunk decomposition
    const int qr = w * 16 + (lane & 15);
    const int qbit = lane >> 4;
    const int kr = (lane & 7) + ((lane >> 4) << 3);  // + np*16
    const int kbit = (lane >> 3) & 1;
    const int vr = lane & 15;                        // + 16*s
    const int vbit = (lane >> 4) & 1;

    uint32_t aq[4][4];  // Q fragments, hoisted

    for (int kt = 0; kt < nkt; ++kt) {
        if (kt + 1 < nkt) cp_wait<1>(); else cp_wait<0>();
        __syncthreads();
        if (kt + 2 < nkt) issueKV(kt + 2, (kt + 2) % 3);
        if (kt == 0) {
#pragma unroll
            for (int s = 0; s < 4; ++s)
                ldm4(aq[s][0], aq[s][1], aq[s][2], aq[s][3],
                     sQ + swz(qr, 2 * s + qbit));
        }
        const uint32_t Ks = sb + 16384 + (kt % 3) * 16384;
        const uint32_t Vs = Ks + 8192;

        // S = Q K^T  (warp: 16 rows x 64 kv cols)
        float Sa[8][4];
#pragma unroll
        for (int n = 0; n < 8; ++n)
#pragma unroll
            for (int j = 0; j < 4; ++j) Sa[n][j] = 0.0f;

#pragma unroll
        for (int s = 0; s < 4; ++s) {
            uint32_t bk[8][2];
#pragma unroll
            for (int np = 0; np < 4; ++np) {
                const int r = kr + np * 16;
                ldm4(bk[2 * np][0], bk[2 * np][1], bk[2 * np + 1][0], bk[2 * np + 1][1],
                     Ks + swz(r, 2 * s + kbit));
            }
#pragma unroll
            for (int n = 0; n < 8; ++n)
                mma16(Sa[n], aq[s][0], aq[s][1], aq[s][2], aq[s][3],
                      bk[n][0], bk[n][1]);
        }

        // causal mask (only the last two kv tiles cross the diagonal)
        if (kt >= 2 * qt) {
#pragma unroll
            for (int n = 0; n < 8; ++n) {
                const int c = kt * 64 + n * 8 + t4 * 2;
                if (c > rlo) Sa[n][0] = -1e30f;
                if (c + 1 > rlo) Sa[n][1] = -1e30f;
                if (c > rlo + 8) Sa[n][2] = -1e30f;
                if (c + 1 > rlo + 8) Sa[n][3] = -1e30f;
            }
        }

        // online softmax (rows g, g+8; quad reduction)
        float mx_lo = -1e30f, mx_hi = -1e30f;
#pragma unroll
        for (int n = 0; n < 8; ++n) {
            mx_lo = fmaxf(mx_lo, fmaxf(Sa[n][0], Sa[n][1]));
            mx_hi = fmaxf(mx_hi, fmaxf(Sa[n][2], Sa[n][3]));
        }
        mx_lo = fmaxf(mx_lo, __shfl_xor_sync(0xffffffffu, mx_lo, 1));
        mx_lo = fmaxf(mx_lo, __shfl_xor_sync(0xffffffffu, mx_lo, 2));
        mx_hi = fmaxf(mx_hi, __shfl_xor_sync(0xffffffffu, mx_hi, 1));
        mx_hi = fmaxf(mx_hi, __shfl_xor_sync(0xffffffffu, mx_hi, 2));
        const float mn_lo = fmaxf(m_lo, mx_lo);
        const float mn_hi = fmaxf(m_hi, mx_hi);
        const float al_lo = __expf(m_lo - mn_lo);
        const float al_hi = __expf(m_hi - mn_hi);
        m_lo = mn_lo;
        m_hi = mn_hi;
        float rs_lo = 0.0f, rs_hi = 0.0f;
#pragma unroll
        for (int n = 0; n < 8; ++n) {
            Sa[n][0] = __expf(Sa[n][0] - mn_lo);
            Sa[n][1] = __expf(Sa[n][1] - mn_lo);
            Sa[n][2] = __expf(Sa[n][2] - mn_hi);
            Sa[n][3] = __expf(Sa[n][3] - mn_hi);
            rs_lo += Sa[n][0] + Sa[n][1];
            rs_hi += Sa[n][2] + Sa[n][3];
        }
        rs_lo += __shfl_xor_sync(0xffffffffu, rs_lo, 1);
        rs_lo += __shfl_xor_sync(0xffffffffu, rs_lo, 2);
        rs_hi += __shfl_xor_sync(0xffffffffu, rs_hi, 1);
        rs_hi += __shfl_xor_sync(0xffffffffu, rs_hi, 2);
        l_lo = l_lo * al_lo + rs_lo;
        l_hi = l_hi * al_hi + rs_hi;
#pragma unroll
        for (int n = 0; n < 8; ++n) {
            O[n][0] *= al_lo;
            O[n][1] *= al_lo;
            O[n][2] *= al_hi;
            O[n][3] *= al_hi;
        }

        // O += P V : P a-frags directly from S c-frag pairs (fp16 pack)
#pragma unroll
        for (int s = 0; s < 4; ++s) {
            const uint32_t pa0 = packh2(Sa[2 * s][0], Sa[2 * s][1]);
            const uint32_t pa1 = packh2(Sa[2 * s][2], Sa[2 * s][3]);
            const uint32_t pa2 = packh2(Sa[2 * s + 1][0], Sa[2 * s + 1][1]);
            const uint32_t pa3 = packh2(Sa[2 * s + 1][2], Sa[2 * s + 1][3]);
            uint32_t bv[8][2];
#pragma unroll
            for (int vp = 0; vp < 4; ++vp) {
                const int r = 16 * s + vr;
                ldm4t(bv[2 * vp][0], bv[2 * vp][1], bv[2 * vp + 1][0], bv[2 * vp + 1][1],
                      Vs + swz(r, 2 * vp + vbit));
            }
#pragma unroll
            for (int n = 0; n < 8; ++n)
                mma16(O[n], pa0, pa1, pa2, pa3, bv[n][0], bv[n][1]);
        }
    }

    // write y [B,T,C] half
    const float inv_lo = 1.0f / l_lo;
    const float inv_hi = 1.0f / l_hi;
    __half* y0 = g_y + (size_t)(b * TT + rlo) * CC;
    __half* y1 = g_y + (size_t)(b * TT + rlo + 8) * CC;
#pragma unroll
    for (int n = 0; n < 8; ++n) {
        const int c = h * HD + n * 8 + t4 * 2;
        *(__half2*)(y0 + c) = __floats2half2_rn(O[n][0] * inv_lo, O[n][1] * inv_lo);
        *(__half2*)(y1 + c) = __floats2half2_rn(O[n][2] * inv_hi, O[n][3] * inv_hi);
    }
}

// ---------------------------------------------------------------------------
extern "C" void kernel_launch(void* const* d_in, const int* in_sizes, int n_in,
                              void* d_out, int out_size)
{
    (void)in_sizes; (void)n_in; (void)out_size;
    const float* x      = (const float*)d_in[0];
    const float* W_attn = (const float*)d_in[1];
    const float* b_attn = (const float*)d_in[2];
    const float* W_proj = (const float*)d_in[3];
    const float* b_proj = (const float*)d_in[4];
    float* out = (float*)d_out;

    const int smem_gemm = 3 * 32768;  // 98304 B
    const int smem_attn = 16384 + 3 * 16384;  // 65536 B
    cudaFuncSetAttribute(gemm_mma<0, 3072>,
                         cudaFuncAttributeMaxDynamicSharedMemorySize, smem_gemm);
    cudaFuncSetAttribute(gemm_mma<1, 1024>,
                         cudaFuncAttributeMaxDynamicSharedMemorySize, smem_gemm);
    cudaFuncSetAttribute(attn_mma,
                         cudaFuncAttributeMaxDynamicSharedMemorySize, smem_attn);

    // 0) convert inputs to half (+ transpose W)
    prep_x<<<(BB * TT * CC / 4) / 256, 256>>>(x);
    prep_w<<<dim3(3072 / 32, 1024 / 32), dim3(32, 8)>>>(W_attn, 3072, 0);
    prep_w<<<dim3(1024 / 32, 1024 / 32), dim3(32, 8)>>>(W_proj, 1024, 1);

    // 1) QKV GEMM + bias -> q/k/v (half)
    gemm_mma<0, 3072><<<dim3(24, 32), 256, smem_gemm>>>(b_attn, nullptr);

    // 2) causal flash attention -> g_y (half)
    attn_mma<<<dim3(16, HH, BB), 256, smem_attn>>>();

    // 3) output projection + bias -> out (f32)
    gemm_mma<1, 1024><<<dim3(8, 32), 256, smem_gemm>>>(b_proj, out);
}